// round 2
// baseline (speedup 1.0000x reference)
#include <cuda_runtime.h>
#include <math.h>

#define GS   28
#define NB   128
#define NH   64
#define ND   4
#define G5   320
#define KK2  128
#define FCH  512
#define NOUT 10

// Recurrent state: [dir][row][col][batch][h]  (~103 MB each)
__device__ float g_h[ND][GS][GS][NB][NH];
__device__ float g_c[ND][GS][GS][NB][NH];
__device__ float g_z1[NB][FCH];

typedef unsigned long long u64;

__device__ __forceinline__ void fma2(u64 &d, u64 a, u64 b) {
    asm("fma.rn.f32x2 %0, %1, %2, %0;" : "+l"(d) : "l"(a), "l"(b));
}
__device__ __forceinline__ void unpack2(u64 v, float &lo, float &hi) {
    asm("mov.b64 {%0, %1}, %2;" : "=f"(lo), "=f"(hi) : "l"(v));
}
__device__ __forceinline__ float sigf(float x) {
    return 1.0f / (1.0f + __expf(-x));
}
__device__ __forceinline__ float tanh_acc(float x) {
    float e = __expf(-2.0f * fabsf(x));
    float t = (1.0f - e) / (1.0f + e);
    return copysignf(t, x);
}

// One block = one (cell-on-diagonal, dir, 16-h chunk).
// Block GEMM: M=128 (batch) x N=80 (5 gates x 16 h) x K=128 ([h_left,h_up]).
// 128 threads: tx = h-in-chunk (16), ty = row-group (8); each thread owns
// 16 batch rows as 8 adjacent pairs -> packed f32x2 accumulators [8][5].
__global__ __launch_bounds__(128) void cell_kernel(
    int d,
    const float* __restrict__ x,
    const float* __restrict__ Wx,
    const float* __restrict__ U,
    const float* __restrict__ bias)
{
    __shared__ __align__(16) float  As[32][130];   // [k][batch], transposed, padded
    __shared__ __align__(16) float2 Bs[32][80];    // U tile, value duplicated
    __shared__ float xs[NB];

    int blk   = blockIdx.x;
    int chunk = blk & 3;
    int dir   = (blk >> 2) & 3;
    int cell  = blk >> 4;
    int rlo   = d - (GS - 1); if (rlo < 0) rlo = 0;
    int r = rlo + cell;
    int c = d - r;

    int tid = threadIdx.x;
    int tx  = tid & 15;
    int ty  = tid >> 4;           // 0..7
    int h0  = chunk * 16;

    const float* hL = (c > 0) ? &g_h[dir][r][c-1][0][0] : nullptr;
    const float* hU = (r > 0) ? &g_h[dir][r-1][c][0][0] : nullptr;

    // direction -> input pixel coords (flips via indexing)
    int rr = (dir & 2) ? (GS - 1 - r) : r;
    int cc = (dir & 1) ? (GS - 1 - c) : c;
    if (tid < NB) xs[tid] = x[tid * (GS * GS) + rr * GS + cc];

    u64 acc[8][5];
    #pragma unroll
    for (int p = 0; p < 8; ++p)
        #pragma unroll
        for (int g = 0; g < 5; ++g) acc[p][g] = 0ull;

    const float* Ud = U + dir * (KK2 * G5);

    for (int kt = 0; kt < 4; ++kt) {
        const float* src  = (kt < 2) ? hL : hU;   // halves of [h_left, h_up]
        int kofs   = (kt & 1) * 32;
        int kglob0 = kt * 32;
        __syncthreads();
        // A tile (transposed): As[kk][b] = src[b*64 + kofs + kk]
        for (int i = tid; i < NB * 32; i += 128) {
            int b  = i >> 5;
            int kk = i & 31;
            As[kk][b] = src ? src[b * NH + kofs + kk] : 0.0f;
        }
        // B tile: 32 x 80 (5 gates x 16 h columns of this chunk), duplicated
        for (int i = tid; i < 32 * 80; i += 128) {
            int kk   = i / 80;
            int col  = i % 80;
            int gate = col >> 4;
            int hh   = col & 15;
            float v = Ud[(kglob0 + kk) * G5 + gate * 64 + h0 + hh];
            Bs[kk][col] = make_float2(v, v);
        }
        __syncthreads();

        #pragma unroll 8
        for (int kk = 0; kk < 32; ++kk) {
            u64 a[8], bf[5];
            #pragma unroll
            for (int p = 0; p < 8; ++p)
                a[p] = *(const u64*)&As[kk][ty * 16 + 2 * p];
            #pragma unroll
            for (int g = 0; g < 5; ++g)
                bf[g] = *(const u64*)&Bs[kk][g * 16 + tx];
            #pragma unroll
            for (int p = 0; p < 8; ++p)
                #pragma unroll
                for (int g = 0; g < 5; ++g)
                    fma2(acc[p][g], a[p], bf[g]);
        }
    }

    // Fused gate epilogue
    const float* cLp = (c > 0) ? &g_c[dir][r][c-1][0][0] : nullptr;
    const float* cUp = (r > 0) ? &g_c[dir][r-1][c][0][0] : nullptr;
    float* hOut = &g_h[dir][r][c][0][0];
    float* cOut = &g_c[dir][r][c][0][0];

    int hcol = h0 + tx;
    const float* Wxd = Wx   + dir * G5;
    const float* bd  = bias + dir * G5;
    float wxb[5], bb[5];
    #pragma unroll
    for (int g = 0; g < 5; ++g) {
        wxb[g] = Wxd[g * 64 + hcol];
        bb[g]  = bd [g * 64 + hcol];
    }

    #pragma unroll
    for (int p = 0; p < 8; ++p) {
        int row0 = ty * 16 + 2 * p;
        float zl[5], zh[5];
        #pragma unroll
        for (int g = 0; g < 5; ++g) unpack2(acc[p][g], zl[g], zh[g]);
        #pragma unroll
        for (int half = 0; half < 2; ++half) {
            int row = row0 + half;
            float xv = xs[row];
            float z0 = (half ? zh[0] : zl[0]) + xv * wxb[0] + bb[0]; // i
            float z1 = (half ? zh[1] : zl[1]) + xv * wxb[1] + bb[1]; // f_left
            float z2 = (half ? zh[2] : zl[2]) + xv * wxb[2] + bb[2]; // f_up
            float z3 = (half ? zh[3] : zl[3]) + xv * wxb[3] + bb[3]; // o
            float z4 = (half ? zh[4] : zl[4]) + xv * wxb[4] + bb[4]; // g
            float cl = cLp ? cLp[row * NH + hcol] : 0.0f;
            float cu = cUp ? cUp[row * NH + hcol] : 0.0f;
            float cn = sigf(z0) * tanh_acc(z4) + sigf(z1) * cl + sigf(z2) * cu;
            float hn = sigf(z3) * tanh_acc(cn);
            cOut[row * NH + hcol] = cn;
            hOut[row * NH + hcol] = hn;
        }
    }
}

// z1 = relu(hfinal @ W1 + b1); hfinal[b][dir*64+h] = g_h[dir][27][27][b][h]
__global__ void head1_kernel(const float* __restrict__ W1,
                             const float* __restrict__ b1)
{
    __shared__ float a[ND * NH];
    int b = blockIdx.y;
    int n = blockIdx.x * 256 + threadIdx.x;
    {
        int dcol = threadIdx.x;
        int dir = dcol >> 6, hh = dcol & 63;
        a[dcol] = g_h[dir][GS-1][GS-1][b][hh];
    }
    __syncthreads();
    float acc = b1[n];
    #pragma unroll 8
    for (int k = 0; k < ND * NH; ++k)
        acc = fmaf(a[k], W1[k * FCH + n], acc);
    g_z1[b][n] = fmaxf(acc, 0.0f);
}

// out = softmax(z1 @ W2 + b2); one block per batch row, warp per logit
__global__ void head2_kernel(const float* __restrict__ W2,
                             const float* __restrict__ b2,
                             float* __restrict__ out)
{
    __shared__ float logit[NOUT];
    int b    = blockIdx.x;
    int tid  = threadIdx.x;        // 320 threads = 10 warps
    int w    = tid >> 5;
    int lane = tid & 31;
    float acc = 0.0f;
    for (int k = lane; k < FCH; k += 32)
        acc = fmaf(g_z1[b][k], W2[k * NOUT + w], acc);
    #pragma unroll
    for (int o = 16; o; o >>= 1)
        acc += __shfl_down_sync(0xffffffffu, acc, o);
    if (lane == 0) logit[w] = acc + b2[w];
    __syncthreads();
    if (tid == 0) {
        float m = -1e30f;
        #pragma unroll
        for (int j = 0; j < NOUT; ++j) m = fmaxf(m, logit[j]);
        float e[NOUT], s = 0.0f;
        #pragma unroll
        for (int j = 0; j < NOUT; ++j) { e[j] = __expf(logit[j] - m); s += e[j]; }
        float inv = 1.0f / s;
        #pragma unroll
        for (int j = 0; j < NOUT; ++j) out[b * NOUT + j] = e[j] * inv;
    }
}

extern "C" void kernel_launch(void* const* d_in, const int* in_sizes, int n_in,
                              void* d_out, int out_size)
{
    const float* x  = (const float*)d_in[0];
    const float* Wx = (const float*)d_in[1];
    const float* U  = (const float*)d_in[2];
    const float* bb = (const float*)d_in[3];
    const float* W1 = (const float*)d_in[4];
    const float* b1 = (const float*)d_in[5];
    const float* W2 = (const float*)d_in[6];
    const float* b2 = (const float*)d_in[7];
    float* out = (float*)d_out;

    for (int d = 0; d < 2 * GS - 1; ++d) {
        int k = d + 1;
        if (2 * GS - 1 - d < k) k = 2 * GS - 1 - d;
        if (k > GS) k = GS;
        cell_kernel<<<k * 16, 128>>>(d, x, Wx, U, bb);
    }
    head1_kernel<<<dim3(2, NB), 256>>>(W1, b1);
    head2_kernel<<<NB, 320>>>(W2, b2, out);
}

// round 5
// speedup vs baseline: 1.4105x; 1.4105x over previous
#include <cuda_runtime.h>
#include <math.h>

#define GS   28
#define NB   128
#define NH   64
#define ND   4
#define G5   320
#define KK2  128
#define FCH  512
#define NOUT 10
#define NBLK 448          // 28 slots * 4 dirs * 4 chunk16

// Recurrent state: [dir][row][col][batch][h]
__device__ float g_h[ND][GS][GS][NB][NH];
__device__ float g_c[ND][GS][GS][NB][NH];
__device__ float g_z1[NB][FCH];
__device__ unsigned g_gen;
__device__ unsigned g_cnt2;

typedef unsigned long long u64;

__device__ __forceinline__ void fma2(u64 &d, u64 a, u64 b) {
    asm("fma.rn.f32x2 %0, %1, %2, %0;" : "+l"(d) : "l"(a), "l"(b));
}
__device__ __forceinline__ void unpack2(u64 v, float &lo, float &hi) {
    asm("mov.b64 {%0, %1}, %2;" : "=f"(lo), "=f"(hi) : "l"(v));
}
__device__ __forceinline__ float sigf(float x) { return 1.0f / (1.0f + __expf(-x)); }
__device__ __forceinline__ float tanh_acc(float x) {
    float e = __expf(-2.0f * fabsf(x));
    float t = (1.0f - e) / (1.0f + e);
    return copysignf(t, x);
}

__global__ void init_kernel() {
    if (threadIdx.x == 0) { g_gen = 0u; g_cnt2 = 0u; }
}

// Sense-reversing grid barrier. All NBLK blocks must be resident (they are:
// reg-occ forced to 4/SM -> 592 slots >= 448; classic bid->SM round-robin
// places <= 4 blocks per SM in wave 1).
__device__ __forceinline__ void grid_barrier(int tid, unsigned gen) {
    __threadfence();
    __syncthreads();
    if (tid == 0) {
        if (atomicAdd(&g_cnt2, 1u) == NBLK - 1u) {
            g_cnt2 = 0u;
            asm volatile("st.release.gpu.global.b32 [%0], %1;"
                         :: "l"(&g_gen), "r"(gen + 1u) : "memory");
        } else {
            unsigned v;
            do {
                __nanosleep(128);
                asm volatile("ld.acquire.gpu.global.b32 %0, [%1];"
                             : "=r"(v) : "l"(&g_gen) : "memory");
            } while (v == gen);
        }
    }
    __syncthreads();
    __threadfence();
}

// Persistent wavefront kernel: R1 cell body VERBATIM, one block per
// (diagonal-slot, dir, chunk16), grid barrier between diagonals.
// blk decode identical to R1: chunk = blk&3, dir = (blk>>2)&3, slot = blk>>4.
__global__ __launch_bounds__(128, 4) void mdlstm_wave(
    const float* __restrict__ x,
    const float* __restrict__ Wx,
    const float* __restrict__ U,
    const float* __restrict__ bias)
{
    __shared__ __align__(16) float  As[32][130];   // [k][batch], transposed, padded
    __shared__ __align__(16) float2 Bs[32][80];    // U tile, value duplicated
    __shared__ float xs[NB];

    int blk   = blockIdx.x;
    int chunk = blk & 3;
    int dir   = (blk >> 2) & 3;
    int slot  = blk >> 4;

    int tid = threadIdx.x;
    int tx  = tid & 15;
    int ty  = tid >> 4;           // 0..7
    int h0  = chunk * 16;

    const float* Ud  = U    + dir * (KK2 * G5);
    const float* Wxd = Wx   + dir * G5;
    const float* bd  = bias + dir * G5;

    int hcol = h0 + tx;
    float wxb[5], bb[5];
    #pragma unroll
    for (int g = 0; g < 5; ++g) {
        wxb[g] = Wxd[g * 64 + hcol];
        bb[g]  = bd [g * 64 + hcol];
    }

    unsigned gen = 0u;

    for (int d = 0; d < 2 * GS - 1; ++d) {
        int rlo = d - (GS - 1); if (rlo < 0) rlo = 0;
        int k = d + 1;
        if (2 * GS - 1 - d < k) k = 2 * GS - 1 - d;
        if (k > GS) k = GS;

        if (slot < k) {
            int r = rlo + slot;
            int c = d - r;

            const float* hL = (c > 0) ? &g_h[dir][r][c-1][0][0] : nullptr;
            const float* hU = (r > 0) ? &g_h[dir][r-1][c][0][0] : nullptr;

            int rr = (dir & 2) ? (GS - 1 - r) : r;
            int cc = (dir & 1) ? (GS - 1 - c) : c;
            xs[tid] = x[tid * (GS * GS) + rr * GS + cc];

            u64 acc[8][5];
            #pragma unroll
            for (int p = 0; p < 8; ++p)
                #pragma unroll
                for (int g = 0; g < 5; ++g) acc[p][g] = 0ull;

            for (int kt = 0; kt < 4; ++kt) {
                const float* src  = (kt < 2) ? hL : hU;   // halves of [h_left, h_up]
                int kofs   = (kt & 1) * 32;
                int kglob0 = kt * 32;
                __syncthreads();
                // A tile (transposed): As[kk][b] = src[b*64 + kofs + kk]
                for (int i = tid; i < NB * 32; i += 128) {
                    int b  = i >> 5;
                    int kk = i & 31;
                    As[kk][b] = src ? src[b * NH + kofs + kk] : 0.0f;
                }
                // B tile: 32 x 80 (5 gates x 16 h columns of this chunk), duplicated
                for (int i = tid; i < 32 * 80; i += 128) {
                    int kk   = i / 80;
                    int col  = i % 80;
                    int gate = col >> 4;
                    int hh   = col & 15;
                    float v = Ud[(kglob0 + kk) * G5 + gate * 64 + h0 + hh];
                    Bs[kk][col] = make_float2(v, v);
                }
                __syncthreads();

                #pragma unroll 8
                for (int kk = 0; kk < 32; ++kk) {
                    u64 a[8], bf[5];
                    #pragma unroll
                    for (int p = 0; p < 8; ++p)
                        a[p] = *(const u64*)&As[kk][ty * 16 + 2 * p];
                    #pragma unroll
                    for (int g = 0; g < 5; ++g)
                        bf[g] = *(const u64*)&Bs[kk][g * 16 + tx];
                    #pragma unroll
                    for (int p = 0; p < 8; ++p)
                        #pragma unroll
                        for (int g = 0; g < 5; ++g)
                            fma2(acc[p][g], a[p], bf[g]);
                }
            }

            // Fused gate epilogue (R1 verbatim: c_left and c_up from global)
            const float* cLp = (c > 0) ? &g_c[dir][r][c-1][0][0] : nullptr;
            const float* cUp = (r > 0) ? &g_c[dir][r-1][c][0][0] : nullptr;
            float* hOut = &g_h[dir][r][c][0][0];
            float* cOut = &g_c[dir][r][c][0][0];

            #pragma unroll
            for (int p = 0; p < 8; ++p) {
                int row0 = ty * 16 + 2 * p;
                float zl[5], zh[5];
                #pragma unroll
                for (int g = 0; g < 5; ++g) unpack2(acc[p][g], zl[g], zh[g]);
                #pragma unroll
                for (int half = 0; half < 2; ++half) {
                    int row = row0 + half;
                    float xv = xs[row];
                    float z0 = (half ? zh[0] : zl[0]) + xv * wxb[0] + bb[0]; // i
                    float z1 = (half ? zh[1] : zl[1]) + xv * wxb[1] + bb[1]; // f_left
                    float z2 = (half ? zh[2] : zl[2]) + xv * wxb[2] + bb[2]; // f_up
                    float z3 = (half ? zh[3] : zl[3]) + xv * wxb[3] + bb[3]; // o
                    float z4 = (half ? zh[4] : zl[4]) + xv * wxb[4] + bb[4]; // g
                    float cl = cLp ? cLp[row * NH + hcol] : 0.0f;
                    float cu = cUp ? cUp[row * NH + hcol] : 0.0f;
                    float cn = sigf(z0) * tanh_acc(z4) + sigf(z1) * cl + sigf(z2) * cu;
                    float hn = sigf(z3) * tanh_acc(cn);
                    cOut[row * NH + hcol] = cn;
                    hOut[row * NH + hcol] = hn;
                }
            }
        }

        grid_barrier(tid, gen);
        gen++;
    }
}

// z1 = relu(hfinal @ W1 + b1); hfinal[b][dir*64+h] = g_h[dir][27][27][b][h]
__global__ void head1_kernel(const float* __restrict__ W1,
                             const float* __restrict__ b1)
{
    __shared__ float a[ND * NH];
    int b = blockIdx.y;
    int n = blockIdx.x * 256 + threadIdx.x;
    {
        int dcol = threadIdx.x;
        int dir = dcol >> 6, hh = dcol & 63;
        a[dcol] = g_h[dir][GS - 1][GS - 1][b][hh];
    }
    __syncthreads();
    float acc = b1[n];
    #pragma unroll 8
    for (int k = 0; k < ND * NH; ++k)
        acc = fmaf(a[k], W1[k * FCH + n], acc);
    g_z1[b][n] = fmaxf(acc, 0.0f);
}

// out = softmax(z1 @ W2 + b2)
__global__ void head2_kernel(const float* __restrict__ W2,
                             const float* __restrict__ b2,
                             float* __restrict__ out)
{
    __shared__ float logit[NOUT];
    int b    = blockIdx.x;
    int tid  = threadIdx.x;        // 320 threads = 10 warps
    int w    = tid >> 5;
    int lane = tid & 31;
    float acc = 0.0f;
    for (int k = lane; k < FCH; k += 32)
        acc = fmaf(g_z1[b][k], W2[k * NOUT + w], acc);
    #pragma unroll
    for (int o = 16; o; o >>= 1)
        acc += __shfl_down_sync(0xffffffffu, acc, o);
    if (lane == 0) logit[w] = acc + b2[w];
    __syncthreads();
    if (tid == 0) {
        float m = -1e30f;
        #pragma unroll
        for (int j = 0; j < NOUT; ++j) m = fmaxf(m, logit[j]);
        float e[NOUT], s = 0.0f;
        #pragma unroll
        for (int j = 0; j < NOUT; ++j) { e[j] = __expf(logit[j] - m); s += e[j]; }
        float inv = 1.0f / s;
        #pragma unroll
        for (int j = 0; j < NOUT; ++j) out[b * NOUT + j] = e[j] * inv;
    }
}

extern "C" void kernel_launch(void* const* d_in, const int* in_sizes, int n_in,
                              void* d_out, int out_size)
{
    const float* x  = (const float*)d_in[0];
    const float* Wx = (const float*)d_in[1];
    const float* U  = (const float*)d_in[2];
    const float* bb = (const float*)d_in[3];
    const float* W1 = (const float*)d_in[4];
    const float* b1 = (const float*)d_in[5];
    const float* W2 = (const float*)d_in[6];
    const float* b2 = (const float*)d_in[7];
    float* out = (float*)d_out;

    init_kernel<<<1, 32>>>();
    mdlstm_wave<<<NBLK, 128>>>(x, Wx, U, bb);
    head1_kernel<<<dim3(2, NB), 256>>>(W1, b1);
    head2_kernel<<<NB, 320>>>(W2, b2, out);
}